// round 1
// baseline (speedup 1.0000x reference)
#include <cuda_runtime.h>
#include <math.h>

#define HQ    16
#define GRP   4
#define TOPK  16
#define DQK   192
#define DV    128
#define QT    16     // queries per CTA tile
#define KTP   66     // padded kT row length (in floats)
#define PPAD  17     // padded p row length
#define NBITS 32     // max kv blocks per sequence (2048/64)
#define SMSCALE 0.07216878364870322f

// dynamic smem layout (floats):
//   qs   [QT*DQK]        = 3072
//   kT   [DQK*KTP]       = 12672
//   vs   [64*DV]         = 8192
//   ps   [64*PPAD]       = 1088
//   ms,ls,scl [QT each]  = 48
//   selm [QT] (uint)     = 16
//   list [QT] (int)      = 16
//   nsel, union          = 2
#define SMEM_FLOATS (QT*DQK + DQK*KTP + 64*DV + 64*PPAD + 3*QT + QT + QT + 2)
#define SMEM_BYTES  (SMEM_FLOATS * 4)

__global__ __launch_bounds__(256, 2)
void selattn_kernel(const float* __restrict__ q, const float* __restrict__ k,
                    const float* __restrict__ v, const int* __restrict__ sidx,
                    const int* __restrict__ slp, float* __restrict__ out) {
    extern __shared__ float sh[];
    float* qs  = sh;                      // [QT][DQK]
    float* kT  = qs + QT * DQK;           // [DQK][KTP]
    float* vs  = kT + DQK * KTP;          // [64][DV]
    float* ps  = vs + 64 * DV;            // [64][PPAD]
    float* ms  = ps + 64 * PPAD;          // [QT]
    float* ls  = ms + QT;                 // [QT]
    float* scl = ls + QT;                 // [QT]
    unsigned* selm = (unsigned*)(scl + QT);   // [QT]
    int* list = (int*)(selm + QT);            // [QT]
    int* nselp = list + QT;                   // [1]
    unsigned* unionp = (unsigned*)(nselp + 1);

    const int S   = slp ? slp[0] : 2048;
    const int qt  = blockIdx.x;           // query tile index
    const int h   = blockIdx.y;           // head
    const int g   = h >> 2;               // selection group
    const int t0  = qt * QT;              // first global query row
    const int seq0 = (t0 / S) * S;        // batch base row
    const int tid = threadIdx.x;
    const int lane = tid & 31;
    const int w    = tid >> 5;

    // ---- load Q tile (float4, coalesced): rows of 192 floats ----
    for (int f = tid; f < QT * (DQK / 4); f += 256) {
        int qi = f / (DQK / 4), dq = f % (DQK / 4);
        ((float4*)qs)[qi * (DQK / 4) + dq] =
            ((const float4*)(q + (size_t)(t0 + qi) * HQ * DQK + (size_t)h * DQK))[dq];
    }
    if (tid < QT) { selm[tid] = 0u; ms[tid] = -1e30f; ls[tid] = 0.0f; }
    __syncthreads();

    // ---- build per-query selection bitmask (dedups duplicate indices) ----
    {
        int qi = tid >> 4, kk = tid & 15;
        int b = sidx[(size_t)(t0 + qi) * (GRP * TOPK) + g * TOPK + kk];
        atomicOr(&selm[qi], 1u << b);
    }
    __syncthreads();
    if (tid < QT) {
        int tq = (t0 + tid) - seq0;          // position within sequence
        int bt = tq >> 6;                    // causal block bound
        unsigned causal = (bt >= 31) ? 0xffffffffu : ((1u << (bt + 1)) - 1u);
        selm[tid] &= causal;
    }
    __syncthreads();
    if (tid == 0) {
        unsigned u = 0;
        #pragma unroll
        for (int i = 0; i < QT; i++) u |= selm[i];
        *unionp = u;
    }
    __syncthreads();
    const unsigned umask = *unionp;

    // ---- static PV ownership: warp = (query quad, dim half); lane = 1 query x 8 dims
    const int quad = w >> 1;
    const int dh   = w & 1;
    const int accq = quad * 4 + (lane >> 3);
    const int d0   = dh * 64 + (lane & 7) * 8;
    float acc[8];
    #pragma unroll
    for (int i = 0; i < 8; i++) acc[i] = 0.0f;

    for (int j = 0; j < NBITS; j++) {
        if (!((umask >> j) & 1u)) continue;
        __syncthreads();   // previous PV done before overwriting kT/vs/ps

        // compact list of queries selecting block j (warp 0)
        if (w == 0) {
            bool act = (lane < QT) && ((selm[lane] >> j) & 1u);
            unsigned bal = __ballot_sync(0xffffffffu, act);
            if (act) list[__popc(bal & ((1u << lane) - 1u))] = lane;
            if (lane == 0) *nselp = __popc(bal);
        }
        if (tid < QT) scl[tid] = 1.0f;
        for (int f = tid; f < 64 * PPAD; f += 256) ps[f] = 0.0f;

        // fill kT (transposed, scalar coalesced reads) and vs (float4)
        {
            const float* kblk = k + ((size_t)(seq0 + j * 64) * HQ + h) * DQK;
            for (int f = tid; f < 64 * DQK; f += 256) {
                int s = f / DQK, d = f - s * DQK;
                kT[d * KTP + s] = kblk[(size_t)s * HQ * DQK + d];
            }
            const float* vblk = v + ((size_t)(seq0 + j * 64) * HQ + h) * DV;
            for (int f = tid; f < 64 * (DV / 4); f += 256) {
                int s = f / (DV / 4), dq = f - s * (DV / 4);
                ((float4*)vs)[s * (DV / 4) + dq] =
                    ((const float4*)(vblk + (size_t)s * HQ * DV))[dq];
            }
        }
        __syncthreads();

        // ---- scores + online softmax: warp handles 2 compacted queries ----
        const int nsel = *nselp;
        const int i0 = w * 2;
        if (i0 < nsel) {
            const bool hasB = (i0 + 1) < nsel;
            const int qa = list[i0];
            const int qb = hasB ? list[i0 + 1] : qa;
            const float* qra = qs + qa * DQK;
            const float* qrb = qs + qb * DQK;
            float sa0 = 0.f, sa1 = 0.f, sb0 = 0.f, sb1 = 0.f;
            #pragma unroll 4
            for (int d = 0; d < DQK; d += 4) {
                const float4 fa = *(const float4*)(qra + d);
                const float4 fb = *(const float4*)(qrb + d);
                const float* kr = kT + d * KTP + 2 * lane;
                const float2 k0 = *(const float2*)(kr);
                const float2 k1 = *(const float2*)(kr + KTP);
                const float2 k2 = *(const float2*)(kr + 2 * KTP);
                const float2 k3 = *(const float2*)(kr + 3 * KTP);
                sa0 += fa.x * k0.x; sa1 += fa.x * k0.y;
                sb0 += fb.x * k0.x; sb1 += fb.x * k0.y;
                sa0 += fa.y * k1.x; sa1 += fa.y * k1.y;
                sb0 += fb.y * k1.x; sb1 += fb.y * k1.y;
                sa0 += fa.z * k2.x; sa1 += fa.z * k2.y;
                sb0 += fb.z * k2.x; sb1 += fb.z * k2.y;
                sa0 += fa.w * k3.x; sa1 += fa.w * k3.y;
                sb0 += fb.w * k3.x; sb1 += fb.w * k3.y;
            }
            const int tqa = t0 + qa - seq0;
            const int tqb = t0 + qb - seq0;
            const int sg0 = j * 64 + 2 * lane;
            sa0 = (sg0     <= tqa) ? sa0 * SMSCALE : -1e30f;
            sa1 = (sg0 + 1 <= tqa) ? sa1 * SMSCALE : -1e30f;
            sb0 = (sg0     <= tqb) ? sb0 * SMSCALE : -1e30f;
            sb1 = (sg0 + 1 <= tqb) ? sb1 * SMSCALE : -1e30f;

            float ma = fmaxf(sa0, sa1), mb = fmaxf(sb0, sb1);
            #pragma unroll
            for (int o = 16; o; o >>= 1) {
                ma = fmaxf(ma, __shfl_xor_sync(0xffffffffu, ma, o));
                mb = fmaxf(mb, __shfl_xor_sync(0xffffffffu, mb, o));
            }
            const float moa = ms[qa];
            const float mna = fmaxf(moa, ma);
            const float pa0 = __expf(sa0 - mna), pa1 = __expf(sa1 - mna);
            const float mob = ms[qb];
            const float mnb = fmaxf(mob, mb);
            const float pb0 = __expf(sb0 - mnb), pb1 = __expf(sb1 - mnb);
            float ra = pa0 + pa1, rb = pb0 + pb1;
            #pragma unroll
            for (int o = 16; o; o >>= 1) {
                ra += __shfl_xor_sync(0xffffffffu, ra, o);
                rb += __shfl_xor_sync(0xffffffffu, rb, o);
            }
            ps[(2 * lane) * PPAD + qa]     = pa0;
            ps[(2 * lane + 1) * PPAD + qa] = pa1;
            if (lane == 0) {
                float sc = __expf(moa - mna);
                scl[qa] = sc; ls[qa] = ls[qa] * sc + ra; ms[qa] = mna;
            }
            if (hasB) {
                ps[(2 * lane) * PPAD + qb]     = pb0;
                ps[(2 * lane + 1) * PPAD + qb] = pb1;
                if (lane == 0) {
                    float sc = __expf(mob - mnb);
                    scl[qb] = sc; ls[qb] = ls[qb] * sc + rb; ms[qb] = mnb;
                }
            }
        }
        __syncthreads();

        // ---- PV: dense accumulate (p==0 for non-selecting queries) ----
        {
            const float sc = scl[accq];
            #pragma unroll
            for (int i = 0; i < 8; i++) acc[i] *= sc;
            const float* vp = vs + d0;
            #pragma unroll 4
            for (int s = 0; s < 64; s++) {
                const float pp = ps[s * PPAD + accq];
                const float4 v0 = *(const float4*)(vp + s * DV);
                const float4 v1 = *(const float4*)(vp + s * DV + 4);
                acc[0] += pp * v0.x; acc[1] += pp * v0.y;
                acc[2] += pp * v0.z; acc[3] += pp * v0.w;
                acc[4] += pp * v1.x; acc[5] += pp * v1.y;
                acc[6] += pp * v1.z; acc[7] += pp * v1.w;
            }
        }
    }

    // ---- finalize (ls last written before a __syncthreads in the loop) ----
    const float invl = 1.0f / ls[accq];
    float* op = out + (size_t)(t0 + accq) * (HQ * DV) + (size_t)h * DV + d0;
    float4 o0, o1;
    o0.x = acc[0] * invl; o0.y = acc[1] * invl; o0.z = acc[2] * invl; o0.w = acc[3] * invl;
    o1.x = acc[4] * invl; o1.y = acc[5] * invl; o1.z = acc[6] * invl; o1.w = acc[7] * invl;
    *(float4*)op = o0;
    *(float4*)(op + 4) = o1;
}

extern "C" void kernel_launch(void* const* d_in, const int* in_sizes, int n_in,
                              void* d_out, int out_size) {
    const float* q   = (const float*)d_in[0];
    const float* k   = (const float*)d_in[1];
    const float* v   = (const float*)d_in[2];
    const int*   idx = (const int*)d_in[3];
    const int*   slp = (n_in >= 6) ? (const int*)d_in[5] : nullptr;
    float* out = (float*)d_out;

    const int T = in_sizes[0] / (HQ * DQK);   // total query rows

    static bool attr_set = false;
    if (!attr_set) {
        cudaFuncSetAttribute(selattn_kernel,
                             cudaFuncAttributeMaxDynamicSharedMemorySize, SMEM_BYTES);
        attr_set = true;
    }

    dim3 grid(T / QT, HQ);
    selattn_kernel<<<grid, 256, SMEM_BYTES>>>(q, k, v, idx, slp, out);
}

// round 3
// speedup vs baseline: 1.9343x; 1.9343x over previous
#include <cuda_runtime.h>
#include <math.h>
#include <string.h>

#define HQ    16
#define GRP   4
#define TOPK  16
#define DQK   192
#define DV    128
#define QT    64     // queries per CTA tile
#define THREADS 512
#define KTP   66     // padded kT row length (floats); EVEN so float2 loads stay 8B-aligned
#define PPAD  65     // padded p row (64 real q + 1 dummy col)
#define NBITS 32     // kv blocks per sequence (2048/64)
#define SMSCALE 0.07216878364870322f

// smem floats:
//  qs   [65][192]  = 12480   (row 64 = dummy query, zeroed)
//  kT   [192][66]  = 12672
//  vs   [64][128]  =  8192
//  ps   [64][65]   =  4160
//  ms/ls/scl [65]  =   195
//  selm [64]u, list[72]i, nsel, union
#define SMEM_FLOATS (12480 + 12672 + 8192 + 4160 + 195 + 64 + 72 + 2)
#define SMEM_BYTES  (SMEM_FLOATS * 4)

// Blackwell packed fp32x2 FMA/MUL (PTX-only; see SASS_QUICKREF "fma.rn.f32x2")
__device__ __forceinline__ void ffma2(float2& d, const float2 a, const float2 b) {
    unsigned long long ua, ub;
    memcpy(&ua, &a, 8); memcpy(&ub, &b, 8);
    unsigned long long* pd = reinterpret_cast<unsigned long long*>(&d);
    asm("fma.rn.f32x2 %0, %1, %2, %0;" : "+l"(*pd) : "l"(ua), "l"(ub));
}
__device__ __forceinline__ void fmul2(float2& d, const float2 b) {
    unsigned long long ub;
    memcpy(&ub, &b, 8);
    unsigned long long* pd = reinterpret_cast<unsigned long long*>(&d);
    asm("mul.rn.f32x2 %0, %0, %1;" : "+l"(*pd) : "l"(ub));
}

__global__ __launch_bounds__(THREADS, 1)
void selattn_kernel(const float* __restrict__ q, const float* __restrict__ k,
                    const float* __restrict__ v, const int* __restrict__ sidx,
                    const int* __restrict__ slp, float* __restrict__ out) {
    extern __shared__ float sh[];
    float* qs  = sh;                       // [65][192]
    float* kT  = qs + 65 * DQK;            // [192][66]
    float* vs  = kT + DQK * KTP;           // [64][128]
    float* ps  = vs + 64 * DV;             // [64][65]
    float* ms  = ps + 64 * PPAD;           // [65]
    float* ls  = ms + 65;                  // [65]
    float* scl = ls + 65;                  // [65]
    unsigned* selm = (unsigned*)(scl + 65);    // [64]
    int* list = (int*)(selm + 64);             // [72]
    int* nselp = list + 72;
    unsigned* unionp = (unsigned*)(nselp + 1);

    const int S    = slp ? slp[0] : 2048;
    const int qt   = blockIdx.x;
    const int h    = blockIdx.y;
    const int g    = h >> 2;
    const int t0   = qt * QT;
    const int seq0 = (t0 / S) * S;
    const int tid  = threadIdx.x;
    const int lane = tid & 31;
    const int w    = tid >> 5;

    // ---- load Q tile (float4, coalesced), zero dummy row ----
    for (int f = tid; f < QT * (DQK / 4); f += THREADS) {
        int qi = f / (DQK / 4), dq = f % (DQK / 4);
        ((float4*)qs)[qi * (DQK / 4) + dq] =
            ((const float4*)(q + (size_t)(t0 + qi) * HQ * DQK + (size_t)h * DQK))[dq];
    }
    if (tid < DQK) qs[QT * DQK + tid] = 0.0f;
    if (tid < QT)  selm[tid] = 0u;
    if (tid < 65) { ms[tid] = -1e30f; ls[tid] = 0.0f; }
    __syncthreads();

    // ---- per-query selection bitmask (dedup) ----
    for (int f = tid; f < QT * TOPK; f += THREADS) {
        int qi = f >> 4, kk = f & 15;
        int b = sidx[(size_t)(t0 + qi) * (GRP * TOPK) + g * TOPK + kk] & 31;
        atomicOr(&selm[qi], 1u << b);
    }
    __syncthreads();
    if (tid < QT) {
        int tq = (t0 + tid) - seq0;
        int bt = tq >> 6;
        unsigned causal = (bt >= 31) ? 0xffffffffu : ((1u << (bt + 1)) - 1u);
        selm[tid] &= causal;
    }
    __syncthreads();
    if (tid < 32) {
        unsigned u = selm[tid] | selm[tid + 32];
        #pragma unroll
        for (int o = 16; o; o >>= 1) u |= __shfl_xor_sync(0xffffffffu, u, o);
        if (tid == 0) *unionp = u;
    }
    __syncthreads();
    const unsigned umask = *unionp;

    // ---- PV static ownership: warp = 16q x 32d chunk, lane = 1q x 16d ----
    const int pvq  = (w & 3) * 16 + (lane & 15);
    const int pvd  = (w >> 2) * 32 + (lane >> 4) * 16;
    float2 acc[8];
    #pragma unroll
    for (int i = 0; i < 8; i++) acc[i] = make_float2(0.0f, 0.0f);

    for (int j = 0; j < NBITS; j++) {
        if (!((umask >> j) & 1u)) continue;
        __syncthreads();   // prior PV reads of vs/ps/scl done

        // warp 0: reset list + compact queries selecting block j
        if (w == 0) {
            list[lane] = 64; list[lane + 32] = 64;
            if (lane < 8) list[64 + lane] = 64;
            __syncwarp();
            bool a0 = (selm[lane]      >> j) & 1u;
            bool a1 = (selm[lane + 32] >> j) & 1u;
            unsigned b0 = __ballot_sync(0xffffffffu, a0);
            unsigned b1 = __ballot_sync(0xffffffffu, a1);
            unsigned lt = (1u << lane) - 1u;
            if (a0) list[__popc(b0 & lt)] = lane;
            if (a1) list[__popc(b0) + __popc(b1 & lt)] = lane + 32;
            if (lane == 0) *nselp = __popc(b0) + __popc(b1);
        }
        if (tid < 65) scl[tid] = 1.0f;
        // zero ps
        for (int f = tid; f < (64 * PPAD) / 4; f += THREADS)
            ((float4*)ps)[f] = make_float4(0.f, 0.f, 0.f, 0.f);
        // fill kT (transposed: coalesced LDG.32, 2-way-conflict STS) and vs (float4)
        {
            const float* kblk = k + ((size_t)(seq0 + j * 64) * HQ + h) * DQK;
            for (int f = tid; f < 64 * DQK; f += THREADS) {
                int s = f / DQK, d = f - s * DQK;
                kT[d * KTP + s] = kblk[(size_t)s * HQ * DQK + d];
            }
            const float* vblk = v + ((size_t)(seq0 + j * 64) * HQ + h) * DV;
            for (int f = tid; f < 64 * (DV / 4); f += THREADS) {
                int s = f >> 5, c = f & 31;
                ((float4*)vs)[s * 32 + c] =
                    ((const float4*)vblk)[(size_t)s * HQ * (DV / 4) + c];
            }
        }
        __syncthreads();

        // ---- scores + online softmax: warp handles 8 compacted queries x 2 kv/lane ----
        const int nsel = *nselp;
        const int nwarps = (nsel + 7) >> 3;
        if (w < nwarps) {
            int qi[8];
            const float* qp[8];
            #pragma unroll
            for (int u = 0; u < 8; u++) {
                qi[u] = list[w * 8 + u];
                qp[u] = qs + qi[u] * DQK;
            }
            float sa0[8], sa1[8];
            #pragma unroll
            for (int u = 0; u < 8; u++) { sa0[u] = 0.f; sa1[u] = 0.f; }
            const float* kr = kT + 2 * lane;
            #pragma unroll 2
            for (int d = 0; d < DQK; d += 4) {
                const float2 k0 = *(const float2*)(kr + (d + 0) * KTP);
                const float2 k1 = *(const float2*)(kr + (d + 1) * KTP);
                const float2 k2 = *(const float2*)(kr + (d + 2) * KTP);
                const float2 k3 = *(const float2*)(kr + (d + 3) * KTP);
                #pragma unroll
                for (int u = 0; u < 8; u++) {
                    const float4 f = *(const float4*)(qp[u] + d);
                    sa0[u] += f.x * k0.x; sa1[u] += f.x * k0.y;
                    sa0[u] += f.y * k1.x; sa1[u] += f.y * k1.y;
                    sa0[u] += f.z * k2.x; sa1[u] += f.z * k2.y;
                    sa0[u] += f.w * k3.x; sa1[u] += f.w * k3.y;
                }
            }
            const int sg = j * 64 + 2 * lane;
            #pragma unroll
            for (int u = 0; u < 8; u++) {
                const int tq = t0 + qi[u] - seq0;
                float s0 = (sg     <= tq) ? sa0[u] * SMSCALE : -1e30f;
                float s1 = (sg + 1 <= tq) ? sa1[u] * SMSCALE : -1e30f;
                float mx = fmaxf(s0, s1);
                #pragma unroll
                for (int o = 16; o; o >>= 1)
                    mx = fmaxf(mx, __shfl_xor_sync(0xffffffffu, mx, o));
                const float mo = ms[qi[u]];
                const float mn = fmaxf(mo, mx);
                const float p0 = __expf(s0 - mn), p1 = __expf(s1 - mn);
                float r = p0 + p1;
                #pragma unroll
                for (int o = 16; o; o >>= 1)
                    r += __shfl_xor_sync(0xffffffffu, r, o);
                ps[(2 * lane)     * PPAD + qi[u]] = p0;
                ps[(2 * lane + 1) * PPAD + qi[u]] = p1;
                if (lane == 0) {
                    float sc = __expf(mo - mn);
                    scl[qi[u]] = sc;
                    ls[qi[u]] = ls[qi[u]] * sc + r;
                    ms[qi[u]] = mn;
                }
            }
        }
        __syncthreads();

        // ---- PV: dense, packed fp32x2 FMA ----
        {
            const float sc = scl[pvq];
            const float2 scp = make_float2(sc, sc);
            #pragma unroll
            for (int i = 0; i < 8; i++) fmul2(acc[i], scp);
            const float* vbase = vs + pvd;
            #pragma unroll 4
            for (int s = 0; s < 64; s++) {
                const float p = ps[s * PPAD + pvq];
                const float2 pp = make_float2(p, p);
                const float4* vp = (const float4*)(vbase + s * DV);
                const float4 a0 = vp[0], a1 = vp[1], a2 = vp[2], a3 = vp[3];
                ffma2(acc[0], make_float2(a0.x, a0.y), pp);
                ffma2(acc[1], make_float2(a0.z, a0.w), pp);
                ffma2(acc[2], make_float2(a1.x, a1.y), pp);
                ffma2(acc[3], make_float2(a1.z, a1.w), pp);
                ffma2(acc[4], make_float2(a2.x, a2.y), pp);
                ffma2(acc[5], make_float2(a2.z, a2.w), pp);
                ffma2(acc[6], make_float2(a3.x, a3.y), pp);
                ffma2(acc[7], make_float2(a3.z, a3.w), pp);
            }
        }
    }

    // ---- finalize ----
    const float invl = 1.0f / ls[pvq];
    float* op = out + (size_t)(t0 + pvq) * (HQ * DV) + (size_t)h * DV + pvd;
    float4 o0, o1, o2, o3;
    o0.x = acc[0].x * invl; o0.y = acc[0].y * invl; o0.z = acc[1].x * invl; o0.w = acc[1].y * invl;
    o1.x = acc[2].x * invl; o1.y = acc[2].y * invl; o1.z = acc[3].x * invl; o1.w = acc[3].y * invl;
    o2.x = acc[4].x * invl; o2.y = acc[4].y * invl; o2.z = acc[5].x * invl; o2.w = acc[5].y * invl;
    o3.x = acc[6].x * invl; o3.y = acc[6].y * invl; o3.z = acc[7].x * invl; o3.w = acc[7].y * invl;
    *(float4*)(op)      = o0;
    *(float4*)(op + 4)  = o1;
    *(float4*)(op + 8)  = o2;
    *(float4*)(op + 12) = o3;
}

extern "C" void kernel_launch(void* const* d_in, const int* in_sizes, int n_in,
                              void* d_out, int out_size) {
    const float* q   = (const float*)d_in[0];
    const float* k   = (const float*)d_in[1];
    const float* v   = (const float*)d_in[2];
    const int*   idx = (const int*)d_in[3];
    const int*   slp = (n_in >= 6) ? (const int*)d_in[5] : nullptr;
    float* out = (float*)d_out;

    const int T = in_sizes[0] / (HQ * DQK);

    static bool attr_set = false;
    if (!attr_set) {
        cudaFuncSetAttribute(selattn_kernel,
                             cudaFuncAttributeMaxDynamicSharedMemorySize, SMEM_BYTES);
        attr_set = true;
    }

    dim3 grid(T / QT, HQ);
    selattn_kernel<<<grid, THREADS, SMEM_BYTES>>>(q, k, v, idx, slp, out);
}